// round 12
// baseline (speedup 1.0000x reference)
#include <cuda_runtime.h>

#define DD 64
#define HH_ 256
#define WW 256
#define HWSZ 65536
#define DHW 4194304
#define CASC 3

#define TH 16
#define TW 32
#define IWP 38
#define IHP 20
#define NINP (IHP*IWP)      // 760
#define HHP 18
#define HWP 34
#define NHP (HHP*HWP)       // 612
#define HROW 17
#define HODD (HHP*HROW)     // 306

// smem byte offsets
#define OFF_HA 0                       // 2 planes x 612 x 16B
#define OFF_HB (OFF_HA + 2*NHP*16)     // 19584
#define OFF_IN (OFF_HB + 2*NHP*16)     // 39168 ; 4 planes x 760 x f32
#define OFF_W1 (OFF_IN + 4*NINP*4)     // 51328
#define OFF_W2 (OFF_W1 + 27*32)        // 52192
#define OFF_B1 (OFF_W2 + 27*32)        // 53056
#define OFF_B2 (OFF_B1 + 32)           // 53088
#define SMEM_BYTES (OFF_B2 + 16)       // 53104

typedef unsigned long long u64;

__device__ float g_t[DHW];
__device__ float g_z[DHW];
__device__ float g_p[DHW];
__device__ float g_q[DHW];
__device__ float g_s[DHW];
__device__ float g_zb[DHW];

__device__ __forceinline__ u64 pack2(float lo, float hi) {
    u64 r; asm("mov.b64 %0,{%1,%2};" : "=l"(r) : "f"(lo), "f"(hi)); return r;
}
__device__ __forceinline__ void unpack2(u64 v, float& lo, float& hi) {
    asm("mov.b64 {%0,%1},%2;" : "=f"(lo), "=f"(hi) : "l"(v));
}
__device__ __forceinline__ u64 ffma2(u64 a, u64 b, u64 c) {
    u64 r; asm("fma.rn.f32x2 %0,%1,%2,%3;" : "=l"(r) : "l"(a), "l"(b), "l"(c)); return r;
}

// ---------------- K0: init (float4) ----------------
__global__ void k_init(const float* __restrict__ img, float* __restrict__ out) {
    int i4 = blockIdx.x * blockDim.x + threadIdx.x;
    if (i4 < DHW / 4) {
        float4 v = ((const float4*)img)[i4];
        ((float4*)g_t)[i4] = v;
        ((float4*)out)[i4] = v;
        float4 z = make_float4(0.f, 0.f, 0.f, 0.f);
        ((float4*)g_p)[i4] = z; ((float4*)g_q)[i4] = z; ((float4*)g_s)[i4] = z;
    }
}

// ---------------- K1: z = t + (sino - sum_d t)/D  (float4) ----------------
__global__ void k_z(const float* __restrict__ sino) {
    int hw4 = blockIdx.x * blockDim.x + threadIdx.x;
    if (hw4 >= HWSZ / 4) return;
    const float4* t4 = (const float4*)g_t;
    float4* z4 = (float4*)g_z;
    float4 sum = make_float4(0.f, 0.f, 0.f, 0.f);
    #pragma unroll 8
    for (int d = 0; d < DD; d++) {
        float4 v = t4[d * (HWSZ / 4) + hw4];
        sum.x += v.x; sum.y += v.y; sum.z += v.z; sum.w += v.w;
    }
    float4 sn = ((const float4*)sino)[hw4];
    float4 r = make_float4((sn.x - sum.x) * (1.f/DD), (sn.y - sum.y) * (1.f/DD),
                           (sn.z - sum.z) * (1.f/DD), (sn.w - sum.w) * (1.f/DD));
    #pragma unroll 8
    for (int d = 0; d < DD; d++) {
        float4 v = t4[d * (HWSZ / 4) + hw4];
        z4[d * (HWSZ / 4) + hw4] = make_float4(v.x + r.x, v.y + r.y, v.z + r.z, v.w + r.w);
    }
}

// ---------------- K2: single-plane streaming conv, occ 4, channel-half split ----------------
__global__ __launch_bounds__(256, 4) void k_conv(
    const float* __restrict__ W1g, const float* __restrict__ B1g,
    const float* __restrict__ W2g, const float* __restrict__ B2g,
    const float* __restrict__ ntx, const float* __restrict__ nty,
    const float* __restrict__ ntz, const float* __restrict__ nt,
    int casc)
{
    extern __shared__ char sm[];
    ulonglong2* sHA = (ulonglong2*)(sm + OFF_HA);   // 2-plane hidden ring, ch0-3
    ulonglong2* sHB = (ulonglong2*)(sm + OFF_HB);   // ch4-7
    float* sIn = (float*)(sm + OFF_IN);             // fp32 input, 4 planes
    u64* sW1u = (u64*)(sm + OFF_W1);
    u64* sW2u = (u64*)(sm + OFF_W2);
    u64* sB1 = (u64*)(sm + OFF_B1);
    float* sB2 = (float*)(sm + OFF_B2);
    const ulonglong2* sW1v = (const ulonglong2*)sW1u;  // [k*2 + half]
    const ulonglong2* sW2v = (const ulonglong2*)sW2u;

    const int tid = threadIdx.x;
    const int b = blockIdx.z;
    const int h0 = blockIdx.y * TH, w0 = blockIdx.x * TW;

    if (tid < 108) {
        int k = tid >> 2, q = tid & 3;
        sW1u[k * 4 + q] = pack2(W1g[b*216 + (2*q)*27 + k], W1g[b*216 + (2*q+1)*27 + k]);
    } else if (tid < 216) {
        int t = tid - 108; int k = t >> 2, q = t & 3;
        sW2u[k * 4 + q] = pack2(W2g[b*216 + (2*q)*27 + k], W2g[b*216 + (2*q+1)*27 + k]);
    } else if (tid < 220) {
        int q = tid - 216;
        sB1[q] = pack2(B1g[b*8 + 2*q], B1g[b*8 + 2*q + 1]);
    } else if (tid == 220) {
        sB2[0] = B2g[b];
    }
    const float eta = ((b == 0) ? ntx : (b == 1) ? nty : (b == 2) ? ntz : nt)[casc];
    const float* oldv = (b == 0) ? g_p : (b == 1) ? g_q : (b == 2) ? g_s : g_t;
    float*       dst  = (b == 0) ? g_p : (b == 1) ? g_q : (b == 2) ? g_s : g_zb;

    // conv2 pending partial sums: P[0]=od h-1, P[1]=od h, P[2]=od h+1
    u64 P[3][2];
    #pragma unroll
    for (int os = 0; os < 3; os++)
        #pragma unroll
        for (int ws = 0; ws < 2; ws++) P[os][ws] = 0ULL;

    auto load_elem = [&](int id, int j) -> float {
        int i = tid + j * 256;
        if (i >= 720) return 0.f;
        int lh = i / 36, lw = i - lh * 36;
        int gh = h0 + lh - 2, gw = w0 + lw - 2;
        float v = 0.f;
        if (id >= 0 && id < DD && gh >= 0 && gh < HH_ && gw >= 0 && gw < WW) {
            const float* zp = g_z + ((size_t)id * HH_ + gh) * WW + gw;
            if (b == 3) v = zp[0];
            else if (b == 0) { if (gw < WW - 1) v = zp[1] - zp[0]; }
            else if (b == 1) { if (gh < HH_ - 1) v = zp[WW] - zp[0]; }
            else             { if (id < DD - 1) v = zp[HWSZ] - zp[0]; }
        }
        return v;
    };
    auto pre_load = [&](int id, float* R) {
        #pragma unroll
        for (int j = 0; j < 3; j++) R[j] = load_elem(id, j);
    };
    auto sts_plane = [&](int id, const float* R) {
        float* dp = sIn + (id & 3) * NINP;
        #pragma unroll
        for (int j = 0; j < 3; j++) {
            int i = tid + j * 256;
            if (i < 720) {
                int lh = i / 36, lw = i - lh * 36;
                dp[lh * IWP + lw] = R[j];
            }
        }
    };
    auto fill_in = [&](int id) {
        float R[3]; pre_load(id, R); sts_plane(id, R);
    };

    // ---- conv1+relu, ONE channel half (half 0: ch0-3 -> sHA; half 1: ch4-7 -> sHB) ----
    auto comp_half = [&](int h, int half) {
        if (tid >= 216) return;
        ulonglong2* H = (half ? sHB : sHA) + (h & 1) * NHP;
        const int r = tid / 12, seg = tid - 12 * r;
        const int hw0 = seg * 3;
        u64 b0 = sB1[2 * half], b1 = sB1[2 * half + 1];
        u64 acc[3][2];
        #pragma unroll
        for (int j = 0; j < 3; j++) { acc[j][0] = b0; acc[j][1] = b1; }
        #pragma unroll
        for (int kd = 0; kd < 3; kd++) {
            const float* p = sIn + ((h - 1 + kd) & 3) * NINP;
            #pragma unroll
            for (int kh = 0; kh < 3; kh++) {
                int ro = (r + kh) * IWP + hw0;
                u64 va[5];
                #pragma unroll
                for (int m = 0; m < 5; m++) { float f = p[ro + m]; va[m] = pack2(f, f); }
                #pragma unroll
                for (int kw = 0; kw < 3; kw++) {
                    int k = kd * 9 + kh * 3 + kw;
                    ulonglong2 wA = sW1v[k * 2 + half];
                    #pragma unroll
                    for (int j = 0; j < 3; j++) {
                        acc[j][0] = ffma2(wA.x, va[j + kw], acc[j][0]);
                        acc[j][1] = ffma2(wA.y, va[j + kw], acc[j][1]);
                    }
                }
            }
        }
        #pragma unroll
        for (int j = 0; j < 3; j++) {
            int hw = hw0 + j;
            if (hw >= HWP) continue;
            int gh = h0 + r - 1, gw = w0 + hw - 1;
            bool okxy = (gh >= 0 && gh < HH_ && gw >= 0 && gw < WW);
            int idx = r * HROW + (hw >> 1) + ((hw & 1) ? HODD : 0);
            float a, c;
            unpack2(acc[j][0], a, c);
            u64 r0 = okxy ? pack2(fmaxf(a, 0.f), fmaxf(c, 0.f)) : 0ULL;
            unpack2(acc[j][1], a, c);
            u64 r1 = okxy ? pack2(fmaxf(a, 0.f), fmaxf(c, 0.f)) : 0ULL;
            H[idx] = make_ulonglong2(r0, r1);
        }
    };

    // ---- conv2: accumulate one channel half of hidden plane h into P ----
    auto accum_half = [&](int h, int half) {
        const int c = tid & 15, r2 = tid >> 4;
        const ulonglong2* H = (half ? sHB : sHA) + (h & 1) * NHP;
        #pragma unroll
        for (int kh = 0; kh < 3; kh++) {
            int rowb = (r2 + kh) * HROW + c;
            ulonglong2 hv[4];
            hv[0] = H[rowb];
            hv[1] = H[HODD + rowb];
            hv[2] = H[rowb + 1];
            hv[3] = H[HODD + rowb + 1];
            #pragma unroll
            for (int os = 0; os < 3; os++) {           // od = h-1+os -> kd = 2-os
                #pragma unroll
                for (int kw = 0; kw < 3; kw++) {
                    int k = (2 - os) * 9 + kh * 3 + kw;
                    ulonglong2 wa = sW2v[k * 2 + half];
                    #pragma unroll
                    for (int ws = 0; ws < 2; ws++) {
                        int m = kw + ws;
                        P[os][ws] = ffma2(wa.x, hv[m].x, P[os][ws]);
                        P[os][ws] = ffma2(wa.y, hv[m].y, P[os][ws]);
                    }
                }
            }
        }
    };

    auto finalize = [&](int o) {
        const int c = tid & 15, r2 = tid >> 4;
        float bb = sB2[0];
        #pragma unroll
        for (int ws = 0; ws < 2; ws++) {
            float a, cc; unpack2(P[0][ws], a, cc);
            float sum = bb + a + cc;
            size_t gi = ((size_t)o * HH_ + (h0 + r2)) * WW + (w0 + 2 * c + ws);
            float old = oldv[gi];
            dst[gi] = old + eta * (old - sum);
        }
    };
    auto shiftP = [&]() {
        #pragma unroll
        for (int ws = 0; ws < 2; ws++) {
            P[0][ws] = P[1][ws];
            P[1][ws] = P[2][ws];
            P[2][ws] = 0ULL;
        }
    };

    // ---- prologue: planes -1..2 staged; plane 3 preloaded ----
    fill_in(-1); fill_in(0); fill_in(1); fill_in(2);
    float R[3];
    pre_load(3, R);
    __syncthreads();

    // ---- main loop: ONE barrier per plane ----
    for (int h = 0; h < DD; h++) {
        comp_half(h, 0);
        comp_half(h, 1);
        __syncthreads();
        accum_half(h, 0);
        accum_half(h, 1);
        if (h > 0) finalize(h - 1);
        shiftP();
        sts_plane(h + 3, R);
        pre_load(h + 4, R);
    }
    finalize(DD - 1);                // od 63 (hidden 64 contributes zero)
}

// ---------------- K3: t = divT(p,q,s) + z_ (float4) ----------------
__global__ void k_tupd(float* __restrict__ out, int casc) {
    int i4 = blockIdx.x * blockDim.x + threadIdx.x;
    if (i4 >= DHW / 4) return;
    int i = i4 * 4;
    int w = i & (WW - 1);
    int h = (i >> 8) & (HH_ - 1);
    int d = i >> 16;
    const float4* p4 = (const float4*)g_p;
    const float4* q4 = (const float4*)g_q;
    const float4* s4 = (const float4*)g_s;
    float4 v = ((const float4*)g_zb)[i4];
    float4 pc = p4[i4];
    float pm = (w > 0) ? g_p[i - 1] : 0.f;
    v.x += pm   - pc.x;
    v.y += pc.x - pc.y;
    v.z += pc.y - pc.z;
    v.w += pc.z - ((w + 3 < WW - 1) ? pc.w : 0.f);
    float4 qc = q4[i4];
    if (h < HH_ - 1) { v.x -= qc.x; v.y -= qc.y; v.z -= qc.z; v.w -= qc.w; }
    if (h > 0) {
        float4 qu = q4[i4 - WW / 4];
        v.x += qu.x; v.y += qu.y; v.z += qu.z; v.w += qu.w;
    }
    float4 sc = s4[i4];
    if (d < DD - 1) { v.x -= sc.x; v.y -= sc.y; v.z -= sc.z; v.w -= sc.w; }
    if (d > 0) {
        float4 su = s4[i4 - HWSZ / 4];
        v.x += su.x; v.y += su.y; v.z += su.z; v.w += su.w;
    }
    ((float4*)g_t)[i4] = v;
    ((float4*)(out + (size_t)(casc + 1) * DHW))[i4] = v;
}

extern "C" void kernel_launch(void* const* d_in, const int* in_sizes, int n_in,
                              void* d_out, int out_size) {
    const float* image = (const float*)d_in[0];
    const float* sino  = (const float*)d_in[1];
    const float* W1    = (const float*)d_in[2];
    const float* B1    = (const float*)d_in[3];
    const float* W2    = (const float*)d_in[4];
    const float* B2    = (const float*)d_in[5];
    const float* ntx   = (const float*)d_in[6];
    const float* nty   = (const float*)d_in[7];
    const float* ntz   = (const float*)d_in[8];
    const float* nt    = (const float*)d_in[9];
    float* out = (float*)d_out;

    cudaFuncSetAttribute((const void*)k_conv,
                         cudaFuncAttributeMaxDynamicSharedMemorySize, SMEM_BYTES);

    k_init<<<(DHW / 4) / 256, 256>>>(image, out);
    for (int c = 0; c < CASC; c++) {
        k_z<<<(HWSZ / 4) / 256, 256>>>(sino);
        dim3 grid(WW / TW, HH_ / TH, 4);   // 512 CTAs, single wave at occ 4
        k_conv<<<grid, 256, SMEM_BYTES>>>(W1, B1, W2, B2, ntx, nty, ntz, nt, c);
        k_tupd<<<(DHW / 4) / 256, 256>>>(out, c);
    }
}

// round 13
// speedup vs baseline: 1.3271x; 1.3271x over previous
#include <cuda_runtime.h>

#define DD 64
#define HH_ 256
#define WW 256
#define HWSZ 65536
#define DHW 4194304
#define CASC 3

#define TH 16
#define TW 32
#define IWP 38
#define IHP 20
#define NINP (IHP*IWP)      // 760
#define HHP 18
#define HWP 34
#define NHP (HHP*HWP)       // 612
#define HROW 17
#define HODD (HHP*HROW)     // 306

// smem byte offsets
#define OFF_HA 0                       // 2 planes x 612 x 16B
#define OFF_HB (OFF_HA + 2*NHP*16)     // 19584
#define OFF_IN (OFF_HB + 2*NHP*16)     // 39168 ; 4 planes x 760 x f32
#define OFF_W1 (OFF_IN + 4*NINP*4)     // 51328
#define OFF_W2 (OFF_W1 + 27*32)        // 52192
#define OFF_B1 (OFF_W2 + 27*32)        // 53056
#define OFF_B2 (OFF_B1 + 32)           // 53088
#define SMEM_BYTES (OFF_B2 + 16)       // 53104

typedef unsigned long long u64;

__device__ float g_t[DHW];
__device__ float g_z[DHW];
__device__ float g_p[DHW];
__device__ float g_q[DHW];
__device__ float g_s[DHW];
__device__ float g_zb[DHW];

__device__ __forceinline__ u64 pack2(float lo, float hi) {
    u64 r; asm("mov.b64 %0,{%1,%2};" : "=l"(r) : "f"(lo), "f"(hi)); return r;
}
__device__ __forceinline__ void unpack2(u64 v, float& lo, float& hi) {
    asm("mov.b64 {%0,%1},%2;" : "=f"(lo), "=f"(hi) : "l"(v));
}
__device__ __forceinline__ u64 ffma2(u64 a, u64 b, u64 c) {
    u64 r; asm("fma.rn.f32x2 %0,%1,%2,%3;" : "=l"(r) : "l"(a), "l"(b), "l"(c)); return r;
}

// ---------------- K0: init (float4) ----------------
__global__ void k_init(const float* __restrict__ img, float* __restrict__ out) {
    int i4 = blockIdx.x * blockDim.x + threadIdx.x;
    if (i4 < DHW / 4) {
        float4 v = ((const float4*)img)[i4];
        ((float4*)g_t)[i4] = v;
        ((float4*)out)[i4] = v;
        float4 z = make_float4(0.f, 0.f, 0.f, 0.f);
        ((float4*)g_p)[i4] = z; ((float4*)g_q)[i4] = z; ((float4*)g_s)[i4] = z;
    }
}

// ---------------- K1: z = t + (sino - sum_d t)/D  (float4) ----------------
__global__ void k_z(const float* __restrict__ sino) {
    int hw4 = blockIdx.x * blockDim.x + threadIdx.x;
    if (hw4 >= HWSZ / 4) return;
    const float4* t4 = (const float4*)g_t;
    float4* z4 = (float4*)g_z;
    float4 sum = make_float4(0.f, 0.f, 0.f, 0.f);
    #pragma unroll 8
    for (int d = 0; d < DD; d++) {
        float4 v = t4[d * (HWSZ / 4) + hw4];
        sum.x += v.x; sum.y += v.y; sum.z += v.z; sum.w += v.w;
    }
    float4 sn = ((const float4*)sino)[hw4];
    float4 r = make_float4((sn.x - sum.x) * (1.f/DD), (sn.y - sum.y) * (1.f/DD),
                           (sn.z - sum.z) * (1.f/DD), (sn.w - sum.w) * (1.f/DD));
    #pragma unroll 8
    for (int d = 0; d < DD; d++) {
        float4 v = t4[d * (HWSZ / 4) + hw4];
        z4[d * (HWSZ / 4) + hw4] = make_float4(v.x + r.x, v.y + r.y, v.z + r.z, v.w + r.w);
    }
}

// ---------------- K2: streaming conv, occ 4, depth-split (2 halves) ----------------
__global__ __launch_bounds__(256, 4) void k_conv(
    const float* __restrict__ W1g, const float* __restrict__ B1g,
    const float* __restrict__ W2g, const float* __restrict__ B2g,
    const float* __restrict__ ntx, const float* __restrict__ nty,
    const float* __restrict__ ntz, const float* __restrict__ nt,
    int casc)
{
    extern __shared__ char sm[];
    ulonglong2* sHA = (ulonglong2*)(sm + OFF_HA);   // 2-plane hidden ring, ch0-3
    ulonglong2* sHB = (ulonglong2*)(sm + OFF_HB);   // ch4-7
    float* sIn = (float*)(sm + OFF_IN);             // fp32 input, 4 planes
    u64* sW1u = (u64*)(sm + OFF_W1);
    u64* sW2u = (u64*)(sm + OFF_W2);
    u64* sB1 = (u64*)(sm + OFF_B1);
    float* sB2 = (float*)(sm + OFF_B2);
    const ulonglong2* sW1v = (const ulonglong2*)sW1u;
    const ulonglong2* sW2v = (const ulonglong2*)sW2u;

    const int tid = threadIdx.x;
    const int zz = blockIdx.z;
    const int b = zz >> 1;                  // 0=dx 1=dy 2=dz 3=z
    const int half = zz & 1;                // depth half: od in [a, a+32)
    const int a = half * 32;
    const int hstart = half ? a - 1 : 0;    // first hidden plane to process
    const int hend = half ? 63 : 32;        // last hidden plane to process
    const int h0 = blockIdx.y * TH, w0 = blockIdx.x * TW;

    if (tid < 108) {
        int k = tid >> 2, q = tid & 3;
        sW1u[k * 4 + q] = pack2(W1g[b*216 + (2*q)*27 + k], W1g[b*216 + (2*q+1)*27 + k]);
    } else if (tid < 216) {
        int t = tid - 108; int k = t >> 2, q = t & 3;
        sW2u[k * 4 + q] = pack2(W2g[b*216 + (2*q)*27 + k], W2g[b*216 + (2*q+1)*27 + k]);
    } else if (tid < 220) {
        int q = tid - 216;
        sB1[q] = pack2(B1g[b*8 + 2*q], B1g[b*8 + 2*q + 1]);
    } else if (tid == 220) {
        sB2[0] = B2g[b];
    }
    const float eta = ((b == 0) ? ntx : (b == 1) ? nty : (b == 2) ? ntz : nt)[casc];
    const float* oldv = (b == 0) ? g_p : (b == 1) ? g_q : (b == 2) ? g_s : g_t;
    float*       dst  = (b == 0) ? g_p : (b == 1) ? g_q : (b == 2) ? g_s : g_zb;

    // conv2 pending partial sums: P[0]=od h-1, P[1]=od h, P[2]=od h+1
    u64 P[3][2];
    #pragma unroll
    for (int os = 0; os < 3; os++)
        #pragma unroll
        for (int ws = 0; ws < 2; ws++) P[os][ws] = 0ULL;

    auto load_elem = [&](int id, int j) -> float {
        int i = tid + j * 256;
        if (i >= 720) return 0.f;
        int lh = i / 36, lw = i - lh * 36;
        int gh = h0 + lh - 2, gw = w0 + lw - 2;
        float v = 0.f;
        if (id >= 0 && id < DD && gh >= 0 && gh < HH_ && gw >= 0 && gw < WW) {
            const float* zp = g_z + ((size_t)id * HH_ + gh) * WW + gw;
            if (b == 3) v = zp[0];
            else if (b == 0) { if (gw < WW - 1) v = zp[1] - zp[0]; }
            else if (b == 1) { if (gh < HH_ - 1) v = zp[WW] - zp[0]; }
            else             { if (id < DD - 1) v = zp[HWSZ] - zp[0]; }
        }
        return v;
    };
    auto pre_load = [&](int id, float* R) {
        #pragma unroll
        for (int j = 0; j < 3; j++) R[j] = load_elem(id, j);
    };
    auto sts_plane = [&](int id, const float* R) {
        float* dp = sIn + (id & 3) * NINP;
        #pragma unroll
        for (int j = 0; j < 3; j++) {
            int i = tid + j * 256;
            if (i < 720) {
                int lh = i / 36, lw = i - lh * 36;
                dp[lh * IWP + lw] = R[j];
            }
        }
    };
    auto fill_in = [&](int id) {
        float R[3]; pre_load(id, R); sts_plane(id, R);
    };

    // ---- conv1+relu for ONE hidden plane h ----
    auto comp_one = [&](int h) {
        if (tid >= 216) return;
        ulonglong2* HA1 = sHA + (h & 1) * NHP;
        ulonglong2* HB1 = sHB + (h & 1) * NHP;
        const int r = tid / 12, seg = tid - 12 * r;
        const int hw0 = seg * 3;
        u64 acc[3][4];
        #pragma unroll
        for (int j = 0; j < 3; j++)
            #pragma unroll
            for (int q = 0; q < 4; q++) acc[j][q] = sB1[q];
        #pragma unroll
        for (int kd = 0; kd < 3; kd++) {
            const float* p = sIn + ((h - 1 + kd) & 3) * NINP;
            #pragma unroll
            for (int kh = 0; kh < 3; kh++) {
                int ro = (r + kh) * IWP + hw0;
                u64 va[5];
                #pragma unroll
                for (int m = 0; m < 5; m++) { float f = p[ro + m]; va[m] = pack2(f, f); }
                #pragma unroll
                for (int kw = 0; kw < 3; kw++) {
                    int k = kd * 9 + kh * 3 + kw;
                    ulonglong2 wA = sW1v[k * 2], wB = sW1v[k * 2 + 1];
                    #pragma unroll
                    for (int j = 0; j < 3; j++) {
                        acc[j][0] = ffma2(wA.x, va[j + kw], acc[j][0]);
                        acc[j][1] = ffma2(wA.y, va[j + kw], acc[j][1]);
                        acc[j][2] = ffma2(wB.x, va[j + kw], acc[j][2]);
                        acc[j][3] = ffma2(wB.y, va[j + kw], acc[j][3]);
                    }
                }
            }
        }
        #pragma unroll
        for (int j = 0; j < 3; j++) {
            int hw = hw0 + j;
            if (hw >= HWP) continue;
            int gh = h0 + r - 1, gw = w0 + hw - 1;
            bool okxy = (gh >= 0 && gh < HH_ && gw >= 0 && gw < WW);
            int idx = r * HROW + (hw >> 1) + ((hw & 1) ? HODD : 0);
            u64 r1[4];
            #pragma unroll
            for (int q = 0; q < 4; q++) {
                float aa, cc;
                unpack2(acc[j][q], aa, cc);
                r1[q] = okxy ? pack2(fmaxf(aa, 0.f), fmaxf(cc, 0.f)) : 0ULL;
            }
            HA1[idx] = make_ulonglong2(r1[0], r1[1]);
            HB1[idx] = make_ulonglong2(r1[2], r1[3]);
        }
    };

    // ---- conv2: accumulate hidden plane h into P[0..2] (od = h-1, h, h+1) ----
    auto accum = [&](int h) {
        const int c = tid & 15, r2 = tid >> 4;
        const ulonglong2* HA = sHA + (h & 1) * NHP;
        const ulonglong2* HB = sHB + (h & 1) * NHP;
        #pragma unroll
        for (int kh = 0; kh < 3; kh++) {
            int rowb = (r2 + kh) * HROW + c;
            ulonglong2 hA[4], hB[4];
            hA[0] = HA[rowb];            hB[0] = HB[rowb];
            hA[1] = HA[HODD + rowb];     hB[1] = HB[HODD + rowb];
            hA[2] = HA[rowb + 1];        hB[2] = HB[rowb + 1];
            hA[3] = HA[HODD + rowb + 1]; hB[3] = HB[HODD + rowb + 1];
            #pragma unroll
            for (int os = 0; os < 3; os++) {           // od = h-1+os -> kd = 2-os
                #pragma unroll
                for (int kw = 0; kw < 3; kw++) {
                    int k = (2 - os) * 9 + kh * 3 + kw;
                    ulonglong2 wa = sW2v[k * 2], wb = sW2v[k * 2 + 1];
                    #pragma unroll
                    for (int ws = 0; ws < 2; ws++) {
                        int m = kw + ws;
                        P[os][ws] = ffma2(wa.x, hA[m].x, P[os][ws]);
                        P[os][ws] = ffma2(wa.y, hA[m].y, P[os][ws]);
                        P[os][ws] = ffma2(wb.x, hB[m].x, P[os][ws]);
                        P[os][ws] = ffma2(wb.y, hB[m].y, P[os][ws]);
                    }
                }
            }
        }
    };

    auto finalize = [&](int o) {
        const int c = tid & 15, r2 = tid >> 4;
        float bb = sB2[0];
        #pragma unroll
        for (int ws = 0; ws < 2; ws++) {
            float aa, cc; unpack2(P[0][ws], aa, cc);
            float sum = bb + aa + cc;
            size_t gi = ((size_t)o * HH_ + (h0 + r2)) * WW + (w0 + 2 * c + ws);
            float old = oldv[gi];
            dst[gi] = old + eta * (old - sum);
        }
    };
    auto shiftP = [&]() {
        #pragma unroll
        for (int ws = 0; ws < 2; ws++) {
            P[0][ws] = P[1][ws];
            P[1][ws] = P[2][ws];
            P[2][ws] = 0ULL;
        }
    };

    // ---- prologue: planes hstart-1..hstart+2 staged; hstart+3 preloaded ----
    fill_in(hstart - 1); fill_in(hstart); fill_in(hstart + 1); fill_in(hstart + 2);
    float R[3];
    pre_load(hstart + 3, R);
    __syncthreads();

    // ---- main loop: ONE barrier per plane, h in [hstart, hend] ----
    for (int h = hstart; h <= hend; h++) {
        comp_one(h);
        __syncthreads();
        accum(h);
        if (h - 1 >= a) finalize(h - 1);
        shiftP();
        sts_plane(h + 3, R);
        pre_load(h + 4, R);
    }
    if (half) finalize(63);              // od 63 (hidden 64 contributes zero)
}

// ---------------- K3: t = divT(p,q,s) + z_ (float4) ----------------
__global__ void k_tupd(float* __restrict__ out, int casc) {
    int i4 = blockIdx.x * blockDim.x + threadIdx.x;
    if (i4 >= DHW / 4) return;
    int i = i4 * 4;
    int w = i & (WW - 1);
    int h = (i >> 8) & (HH_ - 1);
    int d = i >> 16;
    const float4* p4 = (const float4*)g_p;
    const float4* q4 = (const float4*)g_q;
    const float4* s4 = (const float4*)g_s;
    float4 v = ((const float4*)g_zb)[i4];
    float4 pc = p4[i4];
    float pm = (w > 0) ? g_p[i - 1] : 0.f;
    v.x += pm   - pc.x;
    v.y += pc.x - pc.y;
    v.z += pc.y - pc.z;
    v.w += pc.z - ((w + 3 < WW - 1) ? pc.w : 0.f);
    float4 qc = q4[i4];
    if (h < HH_ - 1) { v.x -= qc.x; v.y -= qc.y; v.z -= qc.z; v.w -= qc.w; }
    if (h > 0) {
        float4 qu = q4[i4 - WW / 4];
        v.x += qu.x; v.y += qu.y; v.z += qu.z; v.w += qu.w;
    }
    float4 sc = s4[i4];
    if (d < DD - 1) { v.x -= sc.x; v.y -= sc.y; v.z -= sc.z; v.w -= sc.w; }
    if (d > 0) {
        float4 su = s4[i4 - HWSZ / 4];
        v.x += su.x; v.y += su.y; v.z += su.z; v.w += su.w;
    }
    ((float4*)g_t)[i4] = v;
    ((float4*)(out + (size_t)(casc + 1) * DHW))[i4] = v;
}

extern "C" void kernel_launch(void* const* d_in, const int* in_sizes, int n_in,
                              void* d_out, int out_size) {
    const float* image = (const float*)d_in[0];
    const float* sino  = (const float*)d_in[1];
    const float* W1    = (const float*)d_in[2];
    const float* B1    = (const float*)d_in[3];
    const float* W2    = (const float*)d_in[4];
    const float* B2    = (const float*)d_in[5];
    const float* ntx   = (const float*)d_in[6];
    const float* nty   = (const float*)d_in[7];
    const float* ntz   = (const float*)d_in[8];
    const float* nt    = (const float*)d_in[9];
    float* out = (float*)d_out;

    cudaFuncSetAttribute((const void*)k_conv,
                         cudaFuncAttributeMaxDynamicSharedMemorySize, SMEM_BYTES);

    k_init<<<(DHW / 4) / 256, 256>>>(image, out);
    for (int c = 0; c < CASC; c++) {
        k_z<<<(HWSZ / 4) / 256, 256>>>(sino);
        dim3 grid(WW / TW, HH_ / TH, 8);   // 1024 CTAs: 4 block types x 2 depth halves
        k_conv<<<grid, 256, SMEM_BYTES>>>(W1, B1, W2, B2, ntx, nty, ntz, nt, c);
        k_tupd<<<(DHW / 4) / 256, 256>>>(out, c);
    }
}